// round 11
// baseline (speedup 1.0000x reference)
#include <cuda_runtime.h>
#include <cuda_bf16.h>
#include <cstdint>
#include <cstddef>

#define VOCAB   100000
#define EMB     256
#define NS      256
#define BATCH   16384
#define TBLK    128              // rows per block (2 tiles of 64)
#define MT      64               // rows per tile
#define NBLK    (BATCH / TBLK)   // 128 blocks -> single wave
#define KPAD    264              // bf16 elems per smem row (256+8 -> conflict-free ldmatrix)

__device__ __nv_bfloat16 g_wbf[NS * EMB];   // pre-converted sampled weights (bf16)
__device__ float g_corr[NS];
__device__ float g_partials[NBLK];
__device__ int   g_count = 0;

__device__ __forceinline__ uint32_t smem_u32(const void* p) {
    return (uint32_t)__cvta_generic_to_shared(p);
}

__device__ __forceinline__ void ldsm_x4(uint32_t& r0, uint32_t& r1, uint32_t& r2, uint32_t& r3,
                                        uint32_t addr) {
    asm volatile("ldmatrix.sync.aligned.m8n8.x4.shared.b16 {%0,%1,%2,%3}, [%4];"
                 : "=r"(r0), "=r"(r1), "=r"(r2), "=r"(r3) : "r"(addr));
}

__device__ __forceinline__ void mma_bf16(float& c0, float& c1, float& c2, float& c3,
                                         uint32_t a0, uint32_t a1, uint32_t a2, uint32_t a3,
                                         uint32_t b0, uint32_t b1) {
    asm volatile("mma.sync.aligned.m16n8k16.row.col.f32.bf16.bf16.f32 "
                 "{%0,%1,%2,%3}, {%4,%5,%6,%7}, {%8,%9}, {%0,%1,%2,%3};"
                 : "+f"(c0), "+f"(c1), "+f"(c2), "+f"(c3)
                 : "r"(a0), "r"(a1), "r"(a2), "r"(a3), "r"(b0), "r"(b1));
}

__device__ __forceinline__ uint2 pack_bf16x4(float4 v) {
    __nv_bfloat162 p0 = __floats2bfloat162_rn(v.x, v.y);
    __nv_bfloat162 p1 = __floats2bfloat162_rn(v.z, v.w);
    uint2 u;
    u.x = *(uint32_t*)&p0;
    u.y = *(uint32_t*)&p1;
    return u;
}

__device__ __forceinline__ void stcs128(float* p, float4 v) {
    asm volatile("st.global.cs.v4.f32 [%0], {%1,%2,%3,%4};"
                 :: "l"(p), "f"(v.x), "f"(v.y), "f"(v.z), "f"(v.w) : "memory");
}

// ---- prep: gather+convert W rows to bf16 scratch; precompute corr ----
__global__ void __launch_bounds__(256) w2v_prep(
    const float* __restrict__ ncew,
    const float* __restrict__ nceb,
    const int* __restrict__ sids)
{
    const float INV_LOGV = 1.0f / logf((float)VOCAB + 1.0f);
    int i = blockIdx.x * 256 + threadIdx.x;   // 64*256 = 16384 = NS * (EMB/4) / 4... (16384 chunks)
    int r = i >> 6, c4 = i & 63;              // r: 0..255, c4: 0..63
    int s = sids[r];
    float4 v = __ldg((const float4*)(ncew + (size_t)s * EMB + c4 * 4));
    *(uint2*)(g_wbf + r * EMB + c4 * 4) = pack_bf16x4(v);
    if (i < NS) {
        int si = sids[i];
        float p = (logf((float)si + 2.0f) - logf((float)si + 1.0f)) * INV_LOGV;
        g_corr[i] = nceb[si] - logf((float)NS * p);
    }
}

__global__ void __launch_bounds__(512, 1) w2v_fused(
    const float* __restrict__ emb,
    const float* __restrict__ ncew,
    const float* __restrict__ nceb,
    const int* __restrict__ inputs,
    const int* __restrict__ labels,
    float* __restrict__ out)
{
    extern __shared__ unsigned char smem_raw[];
    __nv_bfloat16* sA = (__nv_bfloat16*)smem_raw;             // [2][MT][KPAD]
    __nv_bfloat16* sW = sA + 2 * MT * KPAD;                   // [NS][KPAD]
    float* sCorr = (float*)(sW + (size_t)NS * KPAD);          // [NS]
    int*   sRow  = (int*)(sCorr + NS);                        // [TBLK]
    float* sRed  = (float*)(sRow + TBLK);                     // [16]

    const int tid  = threadIdx.x;
    const int bid  = blockIdx.x;
    const int R0   = bid * TBLK;
    const float INV_LOGV = 1.0f / logf((float)VOCAB + 1.0f);

    if (tid < TBLK) sRow[tid] = inputs[R0 + tid];
    if (tid < NS)   sCorr[tid] = g_corr[tid];
    __syncthreads();

    const int warp = tid >> 5;   // 0..15
    const int lane = tid & 31;

    // ---- Prefetch batch-0 true-logit label rows (cold DRAM): 4 rows/warp ----
    int    lab0[4];
    float4 t00[4], t01[4];
    #pragma unroll
    for (int i = 0; i < 4; i++) {
        int lr = warp * 8 + i;
        lab0[i] = labels[R0 + lr];
        const float* wr = ncew + (size_t)lab0[i] * EMB + lane * 8;
        t00[i] = __ldg((const float4*)wr);
        t01[i] = __ldg((const float4*)(wr + 4));
    }

    // ---- Gather ALL 128 embed rows: fp32 -> out (streaming), bf16 -> sA ----
    #pragma unroll
    for (int it = 0; it < TBLK * (EMB / 4) / 512; it++) {   // 16 iters
        int i = it * 512 + tid;
        int r = i >> 6, c4 = i & 63;
        float4 v = __ldg((const float4*)(emb + (size_t)sRow[r] * EMB + c4 * 4));
        stcs128((float*)out + (size_t)(R0 + r) * EMB + c4 * 4, v);
        *(uint2*)(sA + r * KPAD + c4 * 4) = pack_bf16x4(v);
    }
    __syncthreads();   // sA complete (needed for smem true-logit reads)

    // ---- W tile: bf16 scratch -> smem via cp.async (no register round-trip) ----
    {
        const uint32_t sWb = smem_u32(sW);
        #pragma unroll
        for (int it = 0; it < NS * EMB * 2 / 16 / 512; it++) {   // 16 iters
            int i = it * 512 + tid;           // 8192 16-byte chunks
            int r = i >> 5, c = i & 31;
            uint32_t dst = sWb + r * (KPAD * 2) + c * 16;
            const __nv_bfloat16* src = g_wbf + r * EMB + c * 8;
            asm volatile("cp.async.cg.shared.global [%0], [%1], 16;"
                         :: "r"(dst), "l"(src));
        }
        asm volatile("cp.async.commit_group;" ::: "memory");
    }

    // ---- Prefetch batch-1 label rows while cp.async streams ----
    int    lab1[4];
    float4 t10[4], t11[4];
    #pragma unroll
    for (int i = 0; i < 4; i++) {
        int lr = warp * 8 + 4 + i;
        lab1[i] = labels[R0 + lr];
        const float* wr = ncew + (size_t)lab1[i] * EMB + lane * 8;
        t10[i] = __ldg((const float4*)wr);
        t11[i] = __ldg((const float4*)(wr + 4));
    }

    // ---- True logits: embed side from smem (bf16), label side from regs ----
    float local = 0.0f;
    #pragma unroll
    for (int b = 0; b < 2; b++) {
        #pragma unroll
        for (int i = 0; i < 4; i++) {
            int lr = warp * 8 + b * 4 + i;
            int lab = b ? lab1[i] : lab0[i];
            float4 w0 = b ? t10[i] : t00[i];
            float4 w1 = b ? t11[i] : t01[i];
            uint4 u = *(const uint4*)(sA + (size_t)lr * KPAD + lane * 8);
            float2 fa = __bfloat1622float2(*(const __nv_bfloat162*)&u.x);
            float2 fb = __bfloat1622float2(*(const __nv_bfloat162*)&u.y);
            float2 fc = __bfloat1622float2(*(const __nv_bfloat162*)&u.z);
            float2 fd = __bfloat1622float2(*(const __nv_bfloat162*)&u.w);
            float s = fa.x * w0.x;
            s = fmaf(fa.y, w0.y, s); s = fmaf(fb.x, w0.z, s); s = fmaf(fb.y, w0.w, s);
            s = fmaf(fc.x, w1.x, s); s = fmaf(fc.y, w1.y, s);
            s = fmaf(fd.x, w1.z, s); s = fmaf(fd.y, w1.w, s);
            #pragma unroll
            for (int o = 16; o; o >>= 1) s += __shfl_xor_sync(0xFFFFFFFFu, s, o);
            if (lane == 0) {
                float p = (logf((float)lab + 2.0f) - logf((float)lab + 1.0f)) * INV_LOGV;
                float t = s + nceb[lab] - logf((float)NS * p);
                local += fmaxf(-t, 0.0f) + __logf(1.0f + __expf(-fabsf(t)));
            }
        }
    }

    asm volatile("cp.async.wait_group 0;" ::: "memory");
    __syncthreads();   // sW ready

    // ================= TILE LOOP: warp (wm, wn) owns 16 rows x 64 samples ====
    const int wm = warp & 3;
    const int wn = warp >> 2;
    const int mrow  = wm * 16;
    const int nbase = wn * 64;
    const int mi = lane >> 3;
    const int arow  = mrow + (mi & 1) * 8 + (lane & 7);
    const int acolb = (mi >> 1) * 8;
    const int bRow  = nbase + (mi >> 1) * 8 + (lane & 7);
    const int bcolb = (mi & 1) * 8;
    const int q = lane & 3;

    #pragma unroll
    for (int t = 0; t < 2; t++) {
        const __nv_bfloat16* sAt = sA + t * MT * KPAD;

        float acc[8][4];
        #pragma unroll
        for (int n = 0; n < 8; n++) {
            acc[n][0] = 0.f; acc[n][1] = 0.f; acc[n][2] = 0.f; acc[n][3] = 0.f;
        }

        #pragma unroll
        for (int k = 0; k < EMB; k += 16) {
            uint32_t a0, a1, a2, a3;
            ldsm_x4(a0, a1, a2, a3, smem_u32(sAt + arow * KPAD + k + acolb));
            #pragma unroll
            for (int nn = 0; nn < 4; nn++) {
                uint32_t b0, b1, b2, b3;   // {b0,b1}=n8-tile 2nn, {b2,b3}=2nn+1
                ldsm_x4(b0, b1, b2, b3, smem_u32(sW + (bRow + nn * 16) * KPAD + k + bcolb));
                mma_bf16(acc[2*nn  ][0], acc[2*nn  ][1], acc[2*nn  ][2], acc[2*nn  ][3],
                         a0, a1, a2, a3, b0, b1);
                mma_bf16(acc[2*nn+1][0], acc[2*nn+1][1], acc[2*nn+1][2], acc[2*nn+1][3],
                         a0, a1, a2, a3, b2, b3);
            }
        }

        // Epilogue: sum max(x,0) + log(prod(1+e^-|x|)) — one __logf per tile
        float prod = 1.0f;
        #pragma unroll
        for (int n = 0; n < 8; n++) {
            int c0 = nbase + n * 8 + q * 2;
            float k0 = sCorr[c0], k1 = sCorr[c0 + 1];
            #pragma unroll
            for (int j = 0; j < 4; j++) {
                float x = acc[n][j] + ((j & 1) ? k1 : k0);
                local += fmaxf(x, 0.0f);
                prod *= 1.0f + __expf(-fabsf(x));
            }
        }
        local += __logf(prod);
    }

    // ---- Deterministic block reduction -> per-block partial ----
    #pragma unroll
    for (int o = 16; o; o >>= 1) local += __shfl_xor_sync(0xFFFFFFFFu, local, o);
    if (lane == 0) sRed[warp] = local;
    __syncthreads();
    __shared__ bool sLast;
    if (tid == 0) {
        float v = 0.f;
        #pragma unroll
        for (int w = 0; w < 16; w++) v += sRed[w];
        g_partials[bid] = v;
        __threadfence();
        int old = atomicAdd(&g_count, 1);
        sLast = (old == NBLK - 1);
    }
    __syncthreads();

    // ---- Last block folds all partials into the scalar ----
    if (sLast) {
        __threadfence();
        float v = (tid < NBLK) ? g_partials[tid] : 0.0f;
        #pragma unroll
        for (int o = 16; o; o >>= 1) v += __shfl_xor_sync(0xFFFFFFFFu, v, o);
        if (lane == 0) sRed[warp] = v;
        __syncthreads();
        if (tid == 0) {
            float t = 0.f;
            #pragma unroll
            for (int w = 0; w < 16; w++) t += sRed[w];
            out[(size_t)BATCH * EMB] = t * (1.0f / (float)BATCH);
            g_count = 0;   // reset for next graph replay
        }
    }
}

extern "C" void kernel_launch(void* const* d_in, const int* in_sizes, int n_in,
                              void* d_out, int out_size) {
    const float* emb    = (const float*)d_in[0];
    const float* ncew   = (const float*)d_in[1];
    const float* nceb   = (const float*)d_in[2];
    const int*   inputs = (const int*)d_in[3];
    const int*   labels = (const int*)d_in[4];
    const int*   sids   = (const int*)d_in[5];
    float* out = (float*)d_out;

    w2v_prep<<<64, 256>>>(ncew, nceb, sids);

    size_t smem = (size_t)(2 * MT + NS) * KPAD * sizeof(__nv_bfloat16)
                + (size_t)NS * sizeof(float)
                + (size_t)TBLK * sizeof(int)
                + 16 * sizeof(float);
    cudaFuncSetAttribute(w2v_fused, cudaFuncAttributeMaxDynamicSharedMemorySize, (int)smem);
    w2v_fused<<<NBLK, 512, smem>>>(emb, ncew, nceb, inputs, labels, out);
}

// round 12
// speedup vs baseline: 1.0251x; 1.0251x over previous
#include <cuda_runtime.h>
#include <cuda_bf16.h>
#include <cstdint>
#include <cstddef>

#define VOCAB   100000
#define EMB     256
#define NS      256
#define BATCH   16384
#define TBLK    128              // rows per block (all resident at once)
#define NHALF   128              // samples per MMA phase
#define NBLK    (BATCH / TBLK)   // 128 blocks -> single wave
#define KPAD    264              // bf16 elems per smem row (256+8 -> conflict-free ldmatrix)

__device__ float g_partials[NBLK];
__device__ int   g_count = 0;

__device__ __forceinline__ uint32_t smem_u32(const void* p) {
    return (uint32_t)__cvta_generic_to_shared(p);
}

__device__ __forceinline__ void ldsm_x4(uint32_t& r0, uint32_t& r1, uint32_t& r2, uint32_t& r3,
                                        uint32_t addr) {
    asm volatile("ldmatrix.sync.aligned.m8n8.x4.shared.b16 {%0,%1,%2,%3}, [%4];"
                 : "=r"(r0), "=r"(r1), "=r"(r2), "=r"(r3) : "r"(addr));
}

__device__ __forceinline__ void mma_bf16(float& c0, float& c1, float& c2, float& c3,
                                         uint32_t a0, uint32_t a1, uint32_t a2, uint32_t a3,
                                         uint32_t b0, uint32_t b1) {
    asm volatile("mma.sync.aligned.m16n8k16.row.col.f32.bf16.bf16.f32 "
                 "{%0,%1,%2,%3}, {%4,%5,%6,%7}, {%8,%9}, {%0,%1,%2,%3};"
                 : "+f"(c0), "+f"(c1), "+f"(c2), "+f"(c3)
                 : "r"(a0), "r"(a1), "r"(a2), "r"(a3), "r"(b0), "r"(b1));
}

__device__ __forceinline__ uint2 pack_bf16x4(float4 v) {
    __nv_bfloat162 p0 = __floats2bfloat162_rn(v.x, v.y);
    __nv_bfloat162 p1 = __floats2bfloat162_rn(v.z, v.w);
    uint2 u;
    u.x = *(uint32_t*)&p0;
    u.y = *(uint32_t*)&p1;
    return u;
}

__device__ __forceinline__ void stcs128(float* p, float4 v) {
    asm volatile("st.global.cs.v4.f32 [%0], {%1,%2,%3,%4};"
                 :: "l"(p), "f"(v.x), "f"(v.y), "f"(v.z), "f"(v.w) : "memory");
}

__global__ void __launch_bounds__(512, 1) w2v_fused(
    const float* __restrict__ emb,
    const float* __restrict__ ncew,
    const float* __restrict__ nceb,
    const int* __restrict__ inputs,
    const int* __restrict__ labels,
    const int* __restrict__ sids,
    float* __restrict__ out)
{
    extern __shared__ unsigned char smem_raw[];
    __nv_bfloat16* sA = (__nv_bfloat16*)smem_raw;             // [TBLK][KPAD]
    __nv_bfloat16* sW = sA + TBLK * KPAD;                     // [2][NHALF][KPAD]
    float* sCorr = (float*)(sW + (size_t)2 * NHALF * KPAD);   // [NS]
    int*   sRow  = (int*)(sCorr + NS);                        // [TBLK]
    float* sRed  = (float*)(sRow + TBLK);                     // [16]

    const int tid  = threadIdx.x;
    const int bid  = blockIdx.x;
    const int R0   = bid * TBLK;
    const float INV_LOGV = 1.0f / logf((float)VOCAB + 1.0f);

    if (tid < TBLK) sRow[tid] = inputs[R0 + tid];
    if (tid < NS) {
        int s = sids[tid];
        float p = (logf((float)s + 2.0f) - logf((float)s + 1.0f)) * INV_LOGV;
        sCorr[tid] = nceb[s] - logf((float)NS * p);
    }
    __syncthreads();

    const int warp = tid >> 5;   // 0..15
    const int lane = tid & 31;

    // ---- Prefetch batch-0 true-logit label rows (cold DRAM): 4 rows/warp ----
    int    lab0[4];
    float4 t00[4], t01[4];
    #pragma unroll
    for (int i = 0; i < 4; i++) {
        int lr = warp * 8 + i;
        lab0[i] = labels[R0 + lr];
        const float* wr = ncew + (size_t)lab0[i] * EMB + lane * 8;
        t00[i] = __ldg((const float4*)wr);
        t01[i] = __ldg((const float4*)(wr + 4));
    }

    // ---- Gather ALL 128 embed rows: fp32 -> out (streaming), bf16 -> sA ----
    #pragma unroll
    for (int it = 0; it < TBLK * (EMB / 4) / 512; it++) {   // 16 iters
        int i = it * 512 + tid;
        int r = i >> 6, c4 = i & 63;
        float4 v = __ldg((const float4*)(emb + (size_t)sRow[r] * EMB + c4 * 4));
        stcs128((float*)out + (size_t)(R0 + r) * EMB + c4 * 4, v);
        *(uint2*)(sA + r * KPAD + c4 * 4) = pack_bf16x4(v);
    }
    // ---- Gather W half 0 only (samples 0..127) ----
    #pragma unroll
    for (int it = 0; it < NHALF * (EMB / 4) / 512; it++) {  // 16 iters
        int i = it * 512 + tid;
        int r = i >> 6, c4 = i & 63;
        int s = sids[r];
        float4 v = __ldg((const float4*)(ncew + (size_t)s * EMB + c4 * 4));
        *(uint2*)(sW + r * KPAD + c4 * 4) = pack_bf16x4(v);
    }

    // ---- Prefetch batch-1 label rows, then true logits for all 128 rows ----
    int    lab1[4];
    float4 t10[4], t11[4];
    #pragma unroll
    for (int i = 0; i < 4; i++) {
        int lr = warp * 8 + 4 + i;
        lab1[i] = labels[R0 + lr];
        const float* wr = ncew + (size_t)lab1[i] * EMB + lane * 8;
        t10[i] = __ldg((const float4*)wr);
        t11[i] = __ldg((const float4*)(wr + 4));
    }

    float local = 0.0f;
    #pragma unroll
    for (int b = 0; b < 2; b++) {
        #pragma unroll
        for (int i = 0; i < 4; i++) {
            int lr = warp * 8 + b * 4 + i;
            int lab = b ? lab1[i] : lab0[i];
            float4 w0 = b ? t10[i] : t00[i];
            float4 w1 = b ? t11[i] : t01[i];
            const float* er = emb + (size_t)sRow[lr] * EMB + lane * 8;   // L1-hot
            float4 a0 = __ldg((const float4*)er);
            float4 a1 = __ldg((const float4*)(er + 4));
            float s = a0.x * w0.x;
            s = fmaf(a0.y, w0.y, s); s = fmaf(a0.z, w0.z, s); s = fmaf(a0.w, w0.w, s);
            s = fmaf(a1.x, w1.x, s); s = fmaf(a1.y, w1.y, s);
            s = fmaf(a1.z, w1.z, s); s = fmaf(a1.w, w1.w, s);
            #pragma unroll
            for (int o = 16; o; o >>= 1) s += __shfl_xor_sync(0xFFFFFFFFu, s, o);
            if (lane == 0) {
                float p = (logf((float)lab + 2.0f) - logf((float)lab + 1.0f)) * INV_LOGV;
                float t = s + nceb[lab] - logf((float)NS * p);
                local += fmaxf(-t, 0.0f) + __logf(1.0f + __expf(-fabsf(t)));
            }
        }
    }
    __syncthreads();   // sA + sW[half 0] ready

    // ============ MMA halves: warp = (m-group 0..7, n-group 0..1) ============
    const int wm = warp >> 1;
    const int wn = warp & 1;
    const int mrow = wm * 16;
    const int mi = lane >> 3;
    const int arow  = mrow + (mi & 1) * 8 + (lane & 7);
    const int acolb = (mi >> 1) * 8;
    const int bRowL = wn * 64 + (mi >> 1) * 8 + (lane & 7);  // + nn*16, local to half
    const int bcolb = (mi & 1) * 8;
    const int q = lane & 3;

    #pragma unroll
    for (int h = 0; h < 2; h++) {
        const __nv_bfloat16* sWh = sW + h * NHALF * KPAD;
        const int nbase = h * NHALF + wn * 64;   // global sample base for corr

        float acc[8][4];
        #pragma unroll
        for (int n = 0; n < 8; n++) {
            acc[n][0] = 0.f; acc[n][1] = 0.f; acc[n][2] = 0.f; acc[n][3] = 0.f;
        }

        #pragma unroll
        for (int k = 0; k < EMB; k += 16) {
            uint32_t a0, a1, a2, a3;
            ldsm_x4(a0, a1, a2, a3, smem_u32(sA + arow * KPAD + k + acolb));
            #pragma unroll
            for (int nn = 0; nn < 4; nn++) {
                uint32_t b0, b1, b2, b3;   // {b0,b1}=n8-tile 2nn, {b2,b3}=2nn+1
                ldsm_x4(b0, b1, b2, b3, smem_u32(sWh + (bRowL + nn * 16) * KPAD + k + bcolb));
                mma_bf16(acc[2*nn  ][0], acc[2*nn  ][1], acc[2*nn  ][2], acc[2*nn  ][3],
                         a0, a1, a2, a3, b0, b1);
                mma_bf16(acc[2*nn+1][0], acc[2*nn+1][1], acc[2*nn+1][2], acc[2*nn+1][3],
                         a0, a1, a2, a3, b2, b3);
            }
        }

        if (h == 0) {
            // Gather W half 1 NOW: buffer disjoint from sW[0]; its LDG latency
            // drains under the epilogue below. No barrier needed until MMA-1.
            #pragma unroll
            for (int it = 0; it < NHALF * (EMB / 4) / 512; it++) {  // 16 iters
                int i = it * 512 + tid;
                int r = i >> 6, c4 = i & 63;
                int s = sids[NHALF + r];
                float4 v = __ldg((const float4*)(ncew + (size_t)s * EMB + c4 * 4));
                *(uint2*)(sW + (NHALF + r) * KPAD + c4 * 4) = pack_bf16x4(v);
            }
        }

        // Epilogue: sum max(x,0) + log(prod(1+e^-|x|)) — one __logf per half
        float prod = 1.0f;
        #pragma unroll
        for (int n = 0; n < 8; n++) {
            int c0 = nbase + n * 8 + q * 2;
            float k0 = sCorr[c0], k1 = sCorr[c0 + 1];
            #pragma unroll
            for (int j = 0; j < 4; j++) {
                float x = acc[n][j] + ((j & 1) ? k1 : k0);
                local += fmaxf(x, 0.0f);
                prod *= 1.0f + __expf(-fabsf(x));
            }
        }
        local += __logf(prod);

        if (h == 0) __syncthreads();   // sW[half 1] ready for MMA-1
    }

    // ---- Deterministic block reduction -> per-block partial ----
    #pragma unroll
    for (int o = 16; o; o >>= 1) local += __shfl_xor_sync(0xFFFFFFFFu, local, o);
    if (lane == 0) sRed[warp] = local;
    __syncthreads();
    __shared__ bool sLast;
    if (tid == 0) {
        float v = 0.f;
        #pragma unroll
        for (int w = 0; w < 16; w++) v += sRed[w];
        g_partials[bid] = v;
        __threadfence();
        int old = atomicAdd(&g_count, 1);
        sLast = (old == NBLK - 1);
    }
    __syncthreads();

    // ---- Last block folds all partials into the scalar ----
    if (sLast) {
        __threadfence();
        float v = (tid < NBLK) ? g_partials[tid] : 0.0f;
        #pragma unroll
        for (int o = 16; o; o >>= 1) v += __shfl_xor_sync(0xFFFFFFFFu, v, o);
        if (lane == 0) sRed[warp] = v;
        __syncthreads();
        if (tid == 0) {
            float t = 0.f;
            #pragma unroll
            for (int w = 0; w < 16; w++) t += sRed[w];
            out[(size_t)BATCH * EMB] = t * (1.0f / (float)BATCH);
            g_count = 0;   // reset for next graph replay
        }
    }
}

extern "C" void kernel_launch(void* const* d_in, const int* in_sizes, int n_in,
                              void* d_out, int out_size) {
    const float* emb    = (const float*)d_in[0];
    const float* ncew   = (const float*)d_in[1];
    const float* nceb   = (const float*)d_in[2];
    const int*   inputs = (const int*)d_in[3];
    const int*   labels = (const int*)d_in[4];
    const int*   sids   = (const int*)d_in[5];
    float* out = (float*)d_out;

    size_t smem = (size_t)(TBLK + 2 * NHALF) * KPAD * sizeof(__nv_bfloat16)
                + (size_t)NS * sizeof(float)
                + (size_t)TBLK * sizeof(int)
                + 16 * sizeof(float);
    cudaFuncSetAttribute(w2v_fused, cudaFuncAttributeMaxDynamicSharedMemorySize, (int)smem);
    w2v_fused<<<NBLK, 512, smem>>>(emb, ncew, nceb, inputs, labels, sids, out);
}

// round 13
// speedup vs baseline: 1.0932x; 1.0664x over previous
#include <cuda_runtime.h>
#include <cuda_bf16.h>
#include <cstdint>
#include <cstddef>

#define VOCAB   100000
#define EMB     256
#define NS      256
#define BATCH   16384
#define TBLK    128              // rows per block (2 tiles of 64)
#define MT      64               // rows per tile
#define NBLK    (BATCH / TBLK)   // 128 blocks -> single wave
#define KPAD    264              // bf16 elems per smem row (256+8 -> conflict-free ldmatrix)

__device__ float g_partials[NBLK];
__device__ int   g_count = 0;

__device__ __forceinline__ uint32_t smem_u32(const void* p) {
    return (uint32_t)__cvta_generic_to_shared(p);
}

__device__ __forceinline__ void ldsm_x4(uint32_t& r0, uint32_t& r1, uint32_t& r2, uint32_t& r3,
                                        uint32_t addr) {
    asm volatile("ldmatrix.sync.aligned.m8n8.x4.shared.b16 {%0,%1,%2,%3}, [%4];"
                 : "=r"(r0), "=r"(r1), "=r"(r2), "=r"(r3) : "r"(addr));
}

__device__ __forceinline__ void mma_bf16(float& c0, float& c1, float& c2, float& c3,
                                         uint32_t a0, uint32_t a1, uint32_t a2, uint32_t a3,
                                         uint32_t b0, uint32_t b1) {
    asm volatile("mma.sync.aligned.m16n8k16.row.col.f32.bf16.bf16.f32 "
                 "{%0,%1,%2,%3}, {%4,%5,%6,%7}, {%8,%9}, {%0,%1,%2,%3};"
                 : "+f"(c0), "+f"(c1), "+f"(c2), "+f"(c3)
                 : "r"(a0), "r"(a1), "r"(a2), "r"(a3), "r"(b0), "r"(b1));
}

__device__ __forceinline__ uint2 pack_bf16x4(float4 v) {
    __nv_bfloat162 p0 = __floats2bfloat162_rn(v.x, v.y);
    __nv_bfloat162 p1 = __floats2bfloat162_rn(v.z, v.w);
    uint2 u;
    u.x = *(uint32_t*)&p0;
    u.y = *(uint32_t*)&p1;
    return u;
}

__device__ __forceinline__ void stcs128(float* p, float4 v) {
    asm volatile("st.global.cs.v4.f32 [%0], {%1,%2,%3,%4};"
                 :: "l"(p), "f"(v.x), "f"(v.y), "f"(v.z), "f"(v.w) : "memory");
}

__global__ void __launch_bounds__(512, 1) w2v_fused(
    const float* __restrict__ emb,
    const float* __restrict__ ncew,
    const float* __restrict__ nceb,
    const int* __restrict__ inputs,
    const int* __restrict__ labels,
    const int* __restrict__ sids,
    float* __restrict__ out)
{
    extern __shared__ unsigned char smem_raw[];
    __nv_bfloat16* sA = (__nv_bfloat16*)smem_raw;             // [2][MT][KPAD]
    __nv_bfloat16* sW = sA + 2 * MT * KPAD;                   // [NS][KPAD]
    float* sCorr = (float*)(sW + (size_t)NS * KPAD);          // [NS]
    int*   sRow  = (int*)(sCorr + NS);                        // [TBLK]
    float* sRed  = (float*)(sRow + TBLK);                     // [16]

    const int tid  = threadIdx.x;
    const int bid  = blockIdx.x;
    const int R0   = bid * TBLK;
    const float INV_LOGV = 1.0f / logf((float)VOCAB + 1.0f);

    if (tid < TBLK) sRow[tid] = inputs[R0 + tid];
    if (tid < NS) {
        int s = sids[tid];
        float p = (logf((float)s + 2.0f) - logf((float)s + 1.0f)) * INV_LOGV;
        sCorr[tid] = nceb[s] - logf((float)NS * p);
    }
    __syncthreads();

    const int warp = tid >> 5;   // 0..15
    const int lane = tid & 31;

    // ---- Prefetch batch-0 label rows (cold DRAM): joins the gather's MLP ----
    int    lab0[4];
    float4 t00[4], t01[4];
    #pragma unroll
    for (int i = 0; i < 4; i++) {
        int lr = warp * 8 + i;
        lab0[i] = labels[R0 + lr];
        const float* wr = ncew + (size_t)lab0[i] * EMB + lane * 8;
        t00[i] = __ldg((const float4*)wr);
        t01[i] = __ldg((const float4*)(wr + 4));
    }

    // ---- FUSED gather: per iteration 1 A-chunk + 4 W-chunks issued together
    //      (two independent LDG streams -> deep MLP), stores afterwards. ----
    #pragma unroll
    for (int g = 0; g < 8; g++) {
        int ia = g * 512 + tid;
        int ra = ia >> 6, ca = ia & 63;
        float4 va = __ldg((const float4*)(emb + (size_t)sRow[ra] * EMB + ca * 4));
        float4 vw[4];
        int rw[4], cw[4];
        #pragma unroll
        for (int j = 0; j < 4; j++) {
            int iw = (g * 4 + j) * 512 + tid;
            rw[j] = iw >> 6; cw[j] = iw & 63;
            vw[j] = __ldg((const float4*)(ncew + (size_t)sids[rw[j]] * EMB + cw[j] * 4));
        }
        stcs128((float*)out + (size_t)(R0 + ra) * EMB + ca * 4, va);
        *(uint2*)(sA + ra * KPAD + ca * 4) = pack_bf16x4(va);
        #pragma unroll
        for (int j = 0; j < 4; j++)
            *(uint2*)(sW + rw[j] * KPAD + cw[j] * 4) = pack_bf16x4(vw[j]);
    }

    // ---- Batch-1 label prefetch BEFORE batch-0 compute (overlaps shfl chains)
    int    lab1[4];
    float4 t10[4], t11[4];
    #pragma unroll
    for (int i = 0; i < 4; i++) {
        int lr = warp * 8 + 4 + i;
        lab1[i] = labels[R0 + lr];
        const float* wr = ncew + (size_t)lab1[i] * EMB + lane * 8;
        t10[i] = __ldg((const float4*)wr);
        t11[i] = __ldg((const float4*)(wr + 4));
    }

    // ---- True logits (embed rows L1-hot from the gather) ----
    float local = 0.0f;
    #pragma unroll
    for (int b = 0; b < 2; b++) {
        #pragma unroll
        for (int i = 0; i < 4; i++) {
            int lr = warp * 8 + b * 4 + i;
            int lab = b ? lab1[i] : lab0[i];
            float4 w0 = b ? t10[i] : t00[i];
            float4 w1 = b ? t11[i] : t01[i];
            const float* er = emb + (size_t)sRow[lr] * EMB + lane * 8;
            float4 a0 = __ldg((const float4*)er);
            float4 a1 = __ldg((const float4*)(er + 4));
            float s = a0.x * w0.x;
            s = fmaf(a0.y, w0.y, s); s = fmaf(a0.z, w0.z, s); s = fmaf(a0.w, w0.w, s);
            s = fmaf(a1.x, w1.x, s); s = fmaf(a1.y, w1.y, s);
            s = fmaf(a1.z, w1.z, s); s = fmaf(a1.w, w1.w, s);
            #pragma unroll
            for (int o = 16; o; o >>= 1) s += __shfl_xor_sync(0xFFFFFFFFu, s, o);
            if (lane == 0) {
                float p = (logf((float)lab + 2.0f) - logf((float)lab + 1.0f)) * INV_LOGV;
                float t = s + nceb[lab] - logf((float)NS * p);
                local += fmaxf(-t, 0.0f) + __logf(1.0f + __expf(-fabsf(t)));
            }
        }
    }
    __syncthreads();   // sA[0] + sW ready

    // ================= TILE LOOP (pipelined, 16x64 warp tiles) ===============
    const int wm = warp & 3;
    const int wn = warp >> 2;
    const int mrow  = wm * 16;
    const int nbase = wn * 64;
    const int mi = lane >> 3;
    const int arow  = mrow + (mi & 1) * 8 + (lane & 7);
    const int acolb = (mi >> 1) * 8;
    const int bRow  = nbase + (mi >> 1) * 8 + (lane & 7);
    const int bcolb = (mi & 1) * 8;
    const int q = lane & 3;

    // Stage registers for tile-1 embed rows: LDGs issue now, consumed after
    // tile-0's MMA — latency fully hidden under compute.
    float4 st[8];
    #pragma unroll
    for (int it = 0; it < 8; it++) {
        int i = it * 512 + tid;
        int r = i >> 6, c4 = i & 63;
        st[it] = __ldg((const float4*)(emb + (size_t)sRow[MT + r] * EMB + c4 * 4));
    }

    #pragma unroll
    for (int t = 0; t < 2; t++) {
        const __nv_bfloat16* sAt = sA + t * MT * KPAD;

        float acc[8][4];
        #pragma unroll
        for (int n = 0; n < 8; n++) {
            acc[n][0] = 0.f; acc[n][1] = 0.f; acc[n][2] = 0.f; acc[n][3] = 0.f;
        }

        #pragma unroll
        for (int k = 0; k < EMB; k += 16) {
            uint32_t a0, a1, a2, a3;
            ldsm_x4(a0, a1, a2, a3, smem_u32(sAt + arow * KPAD + k + acolb));
            #pragma unroll
            for (int nn = 0; nn < 4; nn++) {
                uint32_t b0, b1, b2, b3;   // {b0,b1}=n8-tile 2nn, {b2,b3}=2nn+1
                ldsm_x4(b0, b1, b2, b3, smem_u32(sW + (bRow + nn * 16) * KPAD + k + bcolb));
                mma_bf16(acc[2*nn  ][0], acc[2*nn  ][1], acc[2*nn  ][2], acc[2*nn  ][3],
                         a0, a1, a2, a3, b0, b1);
                mma_bf16(acc[2*nn+1][0], acc[2*nn+1][1], acc[2*nn+1][2], acc[2*nn+1][3],
                         a0, a1, a2, a3, b2, b3);
            }
        }

        // Epilogue: sum max(x,0) + log(prod(1+e^-|x|)) — one __logf per tile
        float prod = 1.0f;
        #pragma unroll
        for (int n = 0; n < 8; n++) {
            int c0 = nbase + n * 8 + q * 2;
            float k0 = sCorr[c0], k1 = sCorr[c0 + 1];
            #pragma unroll
            for (int j = 0; j < 4; j++) {
                float x = acc[n][j] + ((j & 1) ? k1 : k0);
                local += fmaxf(x, 0.0f);
                prod *= 1.0f + __expf(-fabsf(x));
            }
        }
        local += __logf(prod);

        if (t == 0) {
            // Drain stage: fp32 -> out (streaming), bf16 -> sA[1]
            #pragma unroll
            for (int it = 0; it < 8; it++) {
                int i = it * 512 + tid;
                int r = i >> 6, c4 = i & 63;
                stcs128((float*)out + (size_t)(R0 + MT + r) * EMB + c4 * 4, st[it]);
                *(uint2*)(sA + MT * KPAD + r * KPAD + c4 * 4) = pack_bf16x4(st[it]);
            }
            __syncthreads();
        }
    }

    // ---- Deterministic block reduction -> per-block partial ----
    #pragma unroll
    for (int o = 16; o; o >>= 1) local += __shfl_xor_sync(0xFFFFFFFFu, local, o);
    if (lane == 0) sRed[warp] = local;
    __syncthreads();
    __shared__ bool sLast;
    if (tid == 0) {
        float v = 0.f;
        #pragma unroll
        for (int w = 0; w < 16; w++) v += sRed[w];
        g_partials[bid] = v;
        __threadfence();
        int old = atomicAdd(&g_count, 1);
        sLast = (old == NBLK - 1);
    }
    __syncthreads();

    // ---- Last block folds all partials into the scalar ----
    if (sLast) {
        __threadfence();
        float v = (tid < NBLK) ? g_partials[tid] : 0.0f;
        #pragma unroll
        for (int o = 16; o; o >>= 1) v += __shfl_xor_sync(0xFFFFFFFFu, v, o);
        if (lane == 0) sRed[warp] = v;
        __syncthreads();
        if (tid == 0) {
            float t = 0.f;
            #pragma unroll
            for (int w = 0; w < 16; w++) t += sRed[w];
            out[(size_t)BATCH * EMB] = t * (1.0f / (float)BATCH);
            g_count = 0;   // reset for next graph replay
        }
    }
}

extern "C" void kernel_launch(void* const* d_in, const int* in_sizes, int n_in,
                              void* d_out, int out_size) {
    const float* emb    = (const float*)d_in[0];
    const float* ncew   = (const float*)d_in[1];
    const float* nceb   = (const float*)d_in[2];
    const int*   inputs = (const int*)d_in[3];
    const int*   labels = (const int*)d_in[4];
    const int*   sids   = (const int*)d_in[5];
    float* out = (float*)d_out;

    size_t smem = (size_t)(2 * MT + NS) * KPAD * sizeof(__nv_bfloat16)
                + (size_t)NS * sizeof(float)
                + (size_t)TBLK * sizeof(int)
                + 16 * sizeof(float);
    cudaFuncSetAttribute(w2v_fused, cudaFuncAttributeMaxDynamicSharedMemorySize, (int)smem);
    w2v_fused<<<NBLK, 512, smem>>>(emb, ncew, nceb, inputs, labels, sids, out);
}